// round 7
// baseline (speedup 1.0000x reference)
#include <cuda_runtime.h>

#define BB 64
#define CC 256
#define HH 56
#define WW 56
#define SH 52
#define SW 52
#define NPLANES (BB*CC)                 // 16384
#define SEEDS_PER_PLANE (SH*SW)         // 2704
#define OUT_PER_PLANE (HH*WW)           // 3136
#define COUNT_M 51380224                // NPLANES * OUT_PER_PLANE
#define TOTAL_F4 (COUNT_M/4)            // 12845056

#define WPB 8                           // warps per block
#define PPW 2                           // planes per warp (pipelined)
#define PPB (WPB*PPW)                   // 16 planes per block
#define F4PP (SEEDS_PER_PLANE/4)        // 676 float4 per plane
#define NBLK1 (NPLANES/PPB)             // 1024 dilate blocks

// Scratch (no allocations allowed).
__device__ unsigned long long g_dmask[NPLANES * HH];   // 56 row bitmasks/plane -> 7.3 MB
__device__ unsigned int       g_total = 0;             // dropped-count accumulator
__device__ float              g_scale;

// Pack 4 bytes (each holding a 4-bit value in its low nibble) into 16 bits.
__device__ __forceinline__ unsigned pack16(unsigned w) {
    unsigned t = w | (w >> 4);
    t &= 0x00FF00FFu;
    return (t | (t >> 8)) & 0xFFFFu;
}

// ---------------------------------------------------------------------------
// Kernel 1: warp-synchronous, TWO planes per warp, software-pipelined:
// plane B's load batch is issued before plane A's pack/vertical phase, so the
// ALU/smem phase runs under outstanding DRAM loads instead of idling the
// memory pipe. Zero __syncthreads; count via one atomicAdd per warp-plane.
// ---------------------------------------------------------------------------
struct WSlot {
    unsigned char      nib[SH][16];     // 13 nibbles/row, 16B-aligned rows
    unsigned long long rowd[SH];        // horizontally-dilated rows
};

__device__ __forceinline__ void batch_load(float4 (&v)[11], const float4* __restrict__ up,
                                           int b, int lane) {
    #pragma unroll
    for (int j = 0; j < 11; j++) {
        int f = 32 * (11 * b + j) + lane;
        if (f < F4PP) v[j] = __ldcs(&up[f]);
    }
}

__device__ __forceinline__ void batch_consume(const float4 (&v)[11], WSlot* sl,
                                              int b, int lane, float gamma) {
    #pragma unroll
    for (int j = 0; j < 11; j++) {
        int f = 32 * (11 * b + j) + lane;
        if (f < F4PP) {
            unsigned n = (unsigned)(v[j].x < gamma)
                       | ((unsigned)(v[j].y < gamma) << 1)
                       | ((unsigned)(v[j].z < gamma) << 2)
                       | ((unsigned)(v[j].w < gamma) << 3);
            int row = f / 13;
            int cg  = f - row * 13;
            sl->nib[row][cg] = (unsigned char)n;
        }
    }
}

// pack + horizontal + vertical dilation + store + count for one plane slot.
__device__ __forceinline__ void finish_plane(WSlot* sl, int plane, int lane) {
    // Horizontal dilation: one LDS.128 per row, pack to 52 bits, 5-wide OR.
    for (int r = lane; r < SH; r += 32) {
        uint4 w = *(const uint4*)&sl->nib[r][0];
        unsigned long long rr =
              (unsigned long long)(pack16(w.x) | (pack16(w.y) << 16))
            | ((unsigned long long)(pack16(w.z) | (pack16(w.w) << 16)) << 32);
        rr &= 0x000FFFFFFFFFFFFFull;
        unsigned long long t = rr | (rr << 1);
        t |= (t << 2);
        rr = t | (rr << 4);
        sl->rowd[r] = rr;
    }
    __syncwarp();
    // Vertical dilation: output row i = OR of rows [max(0,i-4), min(51,i)].
    unsigned cnt = 0;
    for (int i = lane; i < HH; i += 32) {
        int lo = i - 4; if (lo < 0) lo = 0;
        int hi = i;     if (hi > SH - 1) hi = SH - 1;
        unsigned long long d = 0;
        for (int p = lo; p <= hi; p++) d |= sl->rowd[p];
        g_dmask[(size_t)plane * HH + i] = d;
        cnt += __popcll(d);
    }
    #pragma unroll
    for (int o = 16; o; o >>= 1) cnt += __shfl_down_sync(0xffffffffu, cnt, o);
    if (lane == 0) atomicAdd(&g_total, cnt);
    __syncwarp();
}

__global__ void __launch_bounds__(256, 3) dilate_kernel(const float4* __restrict__ u4,
                                                        const float* __restrict__ gammap) {
    __shared__ WSlot slot[PPB];

    const int warp = threadIdx.x >> 5;
    const int lane = threadIdx.x & 31;
    const int planeA = blockIdx.x * PPB + warp * PPW;   // and planeA+1
    const float gamma = __ldg(gammap);

    const float4* upA = u4 + (size_t)planeA * F4PP;
    const float4* upB = upA + F4PP;
    WSlot* slA = &slot[warp * PPW];
    WSlot* slB = slA + 1;

    float4 v[11];
    // Plane A loads (two batches), staged into smem.
    batch_load(v, upA, 0, lane);  batch_consume(v, slA, 0, lane, gamma);
    batch_load(v, upA, 1, lane);  batch_consume(v, slA, 1, lane, gamma);
    __syncwarp();

    // Issue plane B batch 0, then do plane A's compute under those loads.
    batch_load(v, upB, 0, lane);
    finish_plane(slA, planeA, lane);
    batch_consume(v, slB, 0, lane, gamma);

    batch_load(v, upB, 1, lane);  batch_consume(v, slB, 1, lane, gamma);
    __syncwarp();
    finish_plane(slB, planeA + 1, lane);
}

// ---------------------------------------------------------------------------
// Kernel 2: single thread. Computes the normalization scale in double and
// re-zeros the accumulator (zero-invariant across graph replays).
// ---------------------------------------------------------------------------
__global__ void scale_kernel() {
    unsigned tot = g_total;
    double ones = (double)COUNT_M - (double)tot;   // kept elements
    g_scale = (float)((double)COUNT_M / (ones + 1e-12));
    g_total = 0;
}

// ---------------------------------------------------------------------------
// Kernel 3: apply, ILP-4. Mask bits from the correct 32-bit half of the row
// word (4*cg never straddles bit 32). Streaming hints on the big streams.
// ---------------------------------------------------------------------------
__device__ __forceinline__ void apply_one(const float* __restrict__ x,
                                          float* __restrict__ out,
                                          unsigned f, float s) {
    unsigned plane = f / 784u;                         // 784 f4 per plane
    unsigned rem   = f - plane * 784u;
    unsigned row   = rem / 14u;                        // 14 f4 per 56-wide row
    unsigned cg    = rem - row * 14u;

    const unsigned* dm32 = (const unsigned*)g_dmask;
    unsigned word  = dm32[((size_t)plane * HH + row) * 2 + (cg >> 3)];
    unsigned bits  = (word >> ((cg & 7u) * 4u)) & 0xFu;

    float4 v = __ldcs((const float4*)x + f);
    float4 o;
    o.x = (bits & 1u) ? 0.0f : v.x * s;
    o.y = (bits & 2u) ? 0.0f : v.y * s;
    o.z = (bits & 4u) ? 0.0f : v.z * s;
    o.w = (bits & 8u) ? 0.0f : v.w * s;
    __stcs((float4*)out + f, o);
}

__global__ void __launch_bounds__(256) apply_kernel(const float* __restrict__ x,
                                                    float* __restrict__ out) {
    const float s = g_scale;
    unsigned base = blockIdx.x * 1024u + threadIdx.x;
    apply_one(x, out, base,        s);
    apply_one(x, out, base + 256u, s);
    apply_one(x, out, base + 512u, s);
    apply_one(x, out, base + 768u, s);
}

// ---------------------------------------------------------------------------
extern "C" void kernel_launch(void* const* d_in, const int* in_sizes, int n_in,
                              void* d_out, int out_size) {
    const float* x = nullptr;
    const float* u = nullptr;
    const float* g = nullptr;
    for (int i = 0; i < n_in; i++) {
        if (in_sizes[i] == COUNT_M)                        x = (const float*)d_in[i];
        else if (in_sizes[i] == NPLANES * SEEDS_PER_PLANE) u = (const float*)d_in[i];
        else if (in_sizes[i] == 1)                         g = (const float*)d_in[i];
    }
    float* out = (float*)d_out;

    dilate_kernel<<<NBLK1, 256>>>((const float4*)u, g);
    scale_kernel<<<1, 1>>>();
    apply_kernel<<<TOTAL_F4 / 1024, 256>>>(x, out);
}

// round 9
// speedup vs baseline: 1.0171x; 1.0171x over previous
#include <cuda_runtime.h>

#define BB 64
#define CC 256
#define HH 56
#define WW 56
#define SH 52
#define SW 52
#define NPLANES (BB*CC)                 // 16384
#define SEEDS_PER_PLANE (SH*SW)         // 2704
#define OUT_PER_PLANE (HH*WW)           // 3136
#define COUNT_M 51380224                // NPLANES * OUT_PER_PLANE
#define TOTAL_F4 (COUNT_M/4)            // 12845056

#define P 8                             // planes per block = warps per block
#define F4PP (SEEDS_PER_PLANE/4)        // 676 float4 per plane
#define NBLK1 (NPLANES/P)               // 2048 dilate blocks
#define NWARPS_TOTAL (NBLK1*P)          // 16384 warp arrivals

// Scratch (no allocations allowed).
__device__ unsigned long long g_dmask[NPLANES * HH];   // 56 row bitmasks/plane -> 7.3 MB
__device__ unsigned int       g_total  = 0;            // dropped-count accumulator
__device__ unsigned int       g_ticket = 0;            // warp-arrival ticket (self-resetting)
__device__ float              g_scale;

// Pack 4 bytes (each holding a 4-bit value in its low nibble) into 16 bits.
__device__ __forceinline__ unsigned pack16(unsigned w) {
    unsigned t = w | (w >> 4);
    t &= 0x00FF00FFu;
    return (t | (t >> 8)) & 0xFFFFu;
}

// ---------------------------------------------------------------------------
// Kernel 1: fully warp-synchronous, one plane per warp, zero __syncthreads.
// Loads batched 2x11 float4 for deep MLP. Dropped count -> global atomic.
// The LAST warp to arrive (ticket) computes the normalization scale inline
// and resets the accumulator -- no separate scale kernel. atomicInc with
// wrap NWARPS_TOTAL-1 leaves the ticket at 0 for the next graph replay.
// ---------------------------------------------------------------------------
__global__ void __launch_bounds__(256, 3) dilate_kernel(const float4* __restrict__ u4,
                                                        const float* __restrict__ gammap) {
    __shared__ unsigned char      nib[P][SH][16];   // 13 nibbles/row, 16B rows
    __shared__ unsigned long long rowd[P][SH];      // horizontally-dilated rows

    const int warp = threadIdx.x >> 5;
    const int lane = threadIdx.x & 31;
    const int plane = blockIdx.x * P + warp;
    const float gamma = __ldg(gammap);
    const float4* up = u4 + (size_t)plane * F4PP;

    // Two batches of 11 float4s: issue all loads, then threshold + byte-store.
    #pragma unroll
    for (int b = 0; b < 2; b++) {
        float4 v[11];
        #pragma unroll
        for (int j = 0; j < 11; j++) {
            int f = 32 * (11 * b + j) + lane;
            if (f < F4PP) v[j] = __ldcs(&up[f]);
        }
        #pragma unroll
        for (int j = 0; j < 11; j++) {
            int f = 32 * (11 * b + j) + lane;
            if (f < F4PP) {
                unsigned n = (unsigned)(v[j].x < gamma)
                           | ((unsigned)(v[j].y < gamma) << 1)
                           | ((unsigned)(v[j].z < gamma) << 2)
                           | ((unsigned)(v[j].w < gamma) << 3);
                int row = f / 13;
                int cg  = f - row * 13;
                nib[warp][row][cg] = (unsigned char)n;
            }
        }
    }
    __syncwarp();

    // Horizontal dilation: one LDS.128 per row, nibble-pack to 52 bits,
    // then bit j = OR of seed bits [j-4, j].
    for (int r = lane; r < SH; r += 32) {
        uint4 w = *(const uint4*)&nib[warp][r][0];
        unsigned long long rr =
              (unsigned long long)(pack16(w.x) | (pack16(w.y) << 16))
            | ((unsigned long long)(pack16(w.z) | (pack16(w.w) << 16)) << 32);
        rr &= 0x000FFFFFFFFFFFFFull;     // 52 valid seed bits
        unsigned long long t = rr | (rr << 1);
        t |= (t << 2);
        rr = t | (rr << 4);
        rowd[warp][r] = rr;
    }
    __syncwarp();

    // Vertical dilation: output row i = OR of rows [max(0,i-4), min(51,i)].
    unsigned cnt = 0;
    for (int i = lane; i < HH; i += 32) {
        int lo = i - 4; if (lo < 0) lo = 0;
        int hi = i;     if (hi > SH - 1) hi = SH - 1;
        unsigned long long d = 0;
        for (int p = lo; p <= hi; p++) d |= rowd[warp][p];
        g_dmask[(size_t)plane * HH + i] = d;
        cnt += __popcll(d);
    }

    // Warp-reduce, then one atomic per warp; last warp computes the scale.
    #pragma unroll
    for (int o = 16; o; o >>= 1) cnt += __shfl_down_sync(0xffffffffu, cnt, o);
    if (lane == 0) {
        atomicAdd(&g_total, cnt);
        __threadfence();
        unsigned t = atomicInc(&g_ticket, NWARPS_TOTAL - 1);  // wraps to 0 on last
        if (t == NWARPS_TOTAL - 1) {
            __threadfence();
            unsigned tot = atomicAdd(&g_total, 0u);            // all adds visible
            double ones = (double)COUNT_M - (double)tot;       // kept elements
            g_scale = (float)((double)COUNT_M / (ones + 1e-12));
            g_total = 0;                                       // replay invariant
            __threadfence();
        }
    }
}

// ---------------------------------------------------------------------------
// Kernel 2: apply, ILP-4. Mask bits come from the correct 32-bit half of the
// row word (4*cg never straddles bit 32). Streaming hints on the big streams.
// ---------------------------------------------------------------------------
__device__ __forceinline__ void apply_one(const float* __restrict__ x,
                                          float* __restrict__ out,
                                          unsigned f, float s) {
    unsigned plane = f / 784u;                         // 784 f4 per plane
    unsigned rem   = f - plane * 784u;
    unsigned row   = rem / 14u;                        // 14 f4 per 56-wide row
    unsigned cg    = rem - row * 14u;

    const unsigned* dm32 = (const unsigned*)g_dmask;
    unsigned word  = dm32[((size_t)plane * HH + row) * 2 + (cg >> 3)];
    unsigned bits  = (word >> ((cg & 7u) * 4u)) & 0xFu;

    float4 v = __ldcs((const float4*)x + f);
    float4 o;
    o.x = (bits & 1u) ? 0.0f : v.x * s;
    o.y = (bits & 2u) ? 0.0f : v.y * s;
    o.z = (bits & 4u) ? 0.0f : v.z * s;
    o.w = (bits & 8u) ? 0.0f : v.w * s;
    __stcs((float4*)out + f, o);
}

__global__ void __launch_bounds__(256) apply_kernel(const float* __restrict__ x,
                                                    float* __restrict__ out) {
    const float s = g_scale;
    unsigned base = blockIdx.x * 1024u + threadIdx.x;
    apply_one(x, out, base,        s);
    apply_one(x, out, base + 256u, s);
    apply_one(x, out, base + 512u, s);
    apply_one(x, out, base + 768u, s);
}

// ---------------------------------------------------------------------------
extern "C" void kernel_launch(void* const* d_in, const int* in_sizes, int n_in,
                              void* d_out, int out_size) {
    const float* x = nullptr;
    const float* u = nullptr;
    const float* g = nullptr;
    for (int i = 0; i < n_in; i++) {
        if (in_sizes[i] == COUNT_M)                        x = (const float*)d_in[i];
        else if (in_sizes[i] == NPLANES * SEEDS_PER_PLANE) u = (const float*)d_in[i];
        else if (in_sizes[i] == 1)                         g = (const float*)d_in[i];
    }
    float* out = (float*)d_out;

    dilate_kernel<<<NBLK1, 256>>>((const float4*)u, g);
    apply_kernel<<<TOTAL_F4 / 1024, 256>>>(x, out);
}

// round 11
// speedup vs baseline: 1.0207x; 1.0036x over previous
#include <cuda_runtime.h>

#define BB 64
#define CC 256
#define HH 56
#define WW 56
#define SH 52
#define SW 52
#define NPLANES (BB*CC)                 // 16384
#define SEEDS_PER_PLANE (SH*SW)         // 2704
#define OUT_PER_PLANE (HH*WW)           // 3136
#define COUNT_M 51380224                // NPLANES * OUT_PER_PLANE
#define TOTAL_F4 (COUNT_M/4)            // 12845056

#define P 8                             // planes per block = warps per block
#define F4PP (SEEDS_PER_PLANE/4)        // 676 float4 per plane
#define NBLK1 (NPLANES/P)               // 2048 dilate blocks

// Scratch (no allocations allowed).
__device__ unsigned long long g_dmask[NPLANES * HH];   // 56 row bitmasks/plane -> 7.3 MB
__device__ unsigned int       g_total = 0;             // dropped-count accumulator
__device__ float              g_scale;

// Pack 4 bytes (each holding a 4-bit value in its low nibble) into 16 bits.
__device__ __forceinline__ unsigned pack16(unsigned w) {
    unsigned t = w | (w >> 4);
    t &= 0x00FF00FFu;
    return (t | (t >> 8)) & 0xFFFFu;
}

// ---------------------------------------------------------------------------
// Kernel 1 (measured 32.2us): fully warp-synchronous, one plane per warp,
// zero __syncthreads. Loads batched 2x11 float4 for deep MLP. Per-warp
// dropped count via ONE plain atomicAdd -- no fences (gpu-scope fences emit
// CCTL.IVALL on sm_103a and flush L1, measured -7us regression).
// ---------------------------------------------------------------------------
__global__ void __launch_bounds__(256, 3) dilate_kernel(const float4* __restrict__ u4,
                                                        const float* __restrict__ gammap) {
    __shared__ unsigned char      nib[P][SH][16];   // 13 nibbles/row, 16B rows
    __shared__ unsigned long long rowd[P][SH];      // horizontally-dilated rows

    const int warp = threadIdx.x >> 5;
    const int lane = threadIdx.x & 31;
    const int plane = blockIdx.x * P + warp;
    const float gamma = __ldg(gammap);
    const float4* up = u4 + (size_t)plane * F4PP;

    // Two batches of 11 float4s: issue all loads, then threshold + byte-store.
    #pragma unroll
    for (int b = 0; b < 2; b++) {
        float4 v[11];
        #pragma unroll
        for (int j = 0; j < 11; j++) {
            int f = 32 * (11 * b + j) + lane;
            if (f < F4PP) v[j] = __ldcs(&up[f]);
        }
        #pragma unroll
        for (int j = 0; j < 11; j++) {
            int f = 32 * (11 * b + j) + lane;
            if (f < F4PP) {
                unsigned n = (unsigned)(v[j].x < gamma)
                           | ((unsigned)(v[j].y < gamma) << 1)
                           | ((unsigned)(v[j].z < gamma) << 2)
                           | ((unsigned)(v[j].w < gamma) << 3);
                int row = f / 13;
                int cg  = f - row * 13;
                nib[warp][row][cg] = (unsigned char)n;
            }
        }
    }
    __syncwarp();

    // Horizontal dilation: one LDS.128 per row, nibble-pack to 52 bits,
    // then bit j = OR of seed bits [j-4, j].
    for (int r = lane; r < SH; r += 32) {
        uint4 w = *(const uint4*)&nib[warp][r][0];
        unsigned long long rr =
              (unsigned long long)(pack16(w.x) | (pack16(w.y) << 16))
            | ((unsigned long long)(pack16(w.z) | (pack16(w.w) << 16)) << 32);
        rr &= 0x000FFFFFFFFFFFFFull;     // 52 valid seed bits
        unsigned long long t = rr | (rr << 1);
        t |= (t << 2);
        rr = t | (rr << 4);
        rowd[warp][r] = rr;
    }
    __syncwarp();

    // Vertical dilation: output row i = OR of rows [max(0,i-4), min(51,i)].
    unsigned cnt = 0;
    for (int i = lane; i < HH; i += 32) {
        int lo = i - 4; if (lo < 0) lo = 0;
        int hi = i;     if (hi > SH - 1) hi = SH - 1;
        unsigned long long d = 0;
        for (int p = lo; p <= hi; p++) d |= rowd[warp][p];
        g_dmask[(size_t)plane * HH + i] = d;
        cnt += __popcll(d);
    }

    // Warp-reduce then one fire-and-forget atomic per warp.
    #pragma unroll
    for (int o = 16; o; o >>= 1) cnt += __shfl_down_sync(0xffffffffu, cnt, o);
    if (lane == 0) atomicAdd(&g_total, cnt);
}

// ---------------------------------------------------------------------------
// Kernel 2: single thread. Computes the normalization scale in double and
// re-zeros the accumulator (zero-invariant across graph replays). The kernel
// launch boundary provides the ordering/visibility -- no fences needed.
// ---------------------------------------------------------------------------
__global__ void scale_kernel() {
    unsigned tot = g_total;
    double ones = (double)COUNT_M - (double)tot;   // kept elements
    g_scale = (float)((double)COUNT_M / (ones + 1e-12));
    g_total = 0;
}

// ---------------------------------------------------------------------------
// Kernel 3 (measured 59.8us): apply, ILP-4. Mask bits come from the correct
// 32-bit half of the row word (4*cg never straddles bit 32). Streaming hints
// on the big x/out streams keep the small mask resident in cache.
// ---------------------------------------------------------------------------
__device__ __forceinline__ void apply_one(const float* __restrict__ x,
                                          float* __restrict__ out,
                                          unsigned f, float s) {
    unsigned plane = f / 784u;                         // 784 f4 per plane
    unsigned rem   = f - plane * 784u;
    unsigned row   = rem / 14u;                        // 14 f4 per 56-wide row
    unsigned cg    = rem - row * 14u;

    const unsigned* dm32 = (const unsigned*)g_dmask;
    unsigned word  = dm32[((size_t)plane * HH + row) * 2 + (cg >> 3)];
    unsigned bits  = (word >> ((cg & 7u) * 4u)) & 0xFu;

    float4 v = __ldcs((const float4*)x + f);
    float4 o;
    o.x = (bits & 1u) ? 0.0f : v.x * s;
    o.y = (bits & 2u) ? 0.0f : v.y * s;
    o.z = (bits & 4u) ? 0.0f : v.z * s;
    o.w = (bits & 8u) ? 0.0f : v.w * s;
    __stcs((float4*)out + f, o);
}

__global__ void __launch_bounds__(256) apply_kernel(const float* __restrict__ x,
                                                    float* __restrict__ out) {
    const float s = g_scale;
    unsigned base = blockIdx.x * 1024u + threadIdx.x;
    apply_one(x, out, base,        s);
    apply_one(x, out, base + 256u, s);
    apply_one(x, out, base + 512u, s);
    apply_one(x, out, base + 768u, s);
}

// ---------------------------------------------------------------------------
extern "C" void kernel_launch(void* const* d_in, const int* in_sizes, int n_in,
                              void* d_out, int out_size) {
    const float* x = nullptr;
    const float* u = nullptr;
    const float* g = nullptr;
    for (int i = 0; i < n_in; i++) {
        if (in_sizes[i] == COUNT_M)                        x = (const float*)d_in[i];
        else if (in_sizes[i] == NPLANES * SEEDS_PER_PLANE) u = (const float*)d_in[i];
        else if (in_sizes[i] == 1)                         g = (const float*)d_in[i];
    }
    float* out = (float*)d_out;

    dilate_kernel<<<NBLK1, 256>>>((const float4*)u, g);
    scale_kernel<<<1, 1>>>();
    apply_kernel<<<TOTAL_F4 / 1024, 256>>>(x, out);
}